// round 1
// baseline (speedup 1.0000x reference)
#include <cuda_runtime.h>
#include <cstdint>
#include <float.h>
#include <math.h>

#define EPSV  1e-8f
#define TINYF 1.17549435e-38f

// ---------------------------------------------------------------------------
// JAX threefry2x32, 20 rounds, key = PRNGKey(1) = (0, 1).
// Matches jax._src.prng.threefry2x32 exactly.
// ---------------------------------------------------------------------------
__device__ __forceinline__ unsigned rotl32(unsigned x, int d) {
    return __funnelshift_l(x, x, d);
}

__device__ __forceinline__ uint2 threefry2x32_k01(unsigned c0, unsigned c1) {
    const unsigned k0 = 0u, k1 = 1u, k2 = 0x1BD11BDBu; // 0 ^ 1 ^ 0x1BD11BDA
    unsigned x0 = c0 + k0;
    unsigned x1 = c1 + k1;
#define TF_RND(r) { x0 += x1; x1 = rotl32(x1, (r)); x1 ^= x0; }
    TF_RND(13) TF_RND(15) TF_RND(26) TF_RND(6)   x0 += k1; x1 += k2 + 1u;
    TF_RND(17) TF_RND(29) TF_RND(16) TF_RND(24)  x0 += k2; x1 += k0 + 2u;
    TF_RND(13) TF_RND(15) TF_RND(26) TF_RND(6)   x0 += k0; x1 += k1 + 3u;
    TF_RND(17) TF_RND(29) TF_RND(16) TF_RND(24)  x0 += k1; x1 += k2 + 4u;
    TF_RND(13) TF_RND(15) TF_RND(26) TF_RND(6)   x0 += k2; x1 += k0 + 5u;
#undef TF_RND
    return make_uint2(x0, x1);
}

// Gumbel noise element l of the flat [512*1*16*4] = 32768 array, as JAX makes it:
// counts = iota(32768); halves (i, i+16384); out = concat(r0, r1).
__device__ __forceinline__ float jax_gumbel_at(unsigned l) {
    unsigned i    = (l < 16384u) ? l : (l - 16384u);
    uint2    r    = threefry2x32_k01(i, i + 16384u);
    unsigned bits = (l < 16384u) ? r.x : r.y;
    float u = __uint_as_float((bits >> 9) | 0x3f800000u) - 1.0f; // [0,1)
    u = fmaxf(u + TINYF, TINYF);                                 // uniform(tiny, 1)
    return -logf(-logf(u));
}

// ---------------------------------------------------------------------------
// One CTA per batch b. B=512, C=1024, H=W=8.
// ---------------------------------------------------------------------------
__global__ __launch_bounds__(1024, 2)
void sa_fused_kernel(const float* __restrict__ x,
                     const float* __restrict__ w11,   // [1,1,3,3]
                     const float* __restrict__ w5,    // [4,2,3,3]
                     const float* __restrict__ b5,    // [4]
                     const float* __restrict__ w6,    // [1,4,3,3]
                     const float* __restrict__ b6,    // [1]
                     float* __restrict__ out)
{
    const int b   = blockIdx.x;
    const int tid = threadIdx.x;
    const int s4  = tid & 15;   // float4 spatial index (0..15 -> 64 floats)
    const int g   = tid >> 4;   // channel group (0..63)

    __shared__ float part[64][65];   // per-group partial channel max
    __shared__ float m_sh[64];       // channel max m[h][w]
    __shared__ float wraw[16][4];    // raw window values
    __shared__ float wcl [16][4];    // cleaned window values
    __shared__ float wsc [16][4];    // cleaned + gumbel (argmax scores)
    __shared__ float pre [16];       // pooled 4x4 before conv
    __shared__ float c4s [16];       // 4x4 after 3x3 conv
    __shared__ float out2s[64];      // 8x8 after bilinear resize
    __shared__ float hid [4][64];    // conv5 hidden, relu'd
    __shared__ float gate[64];       // sigmoid gate 8x8

    const float4* xb = (const float4*)(x + ((size_t)b << 16));

    // ---- Phase 1: channel max over C=1024 (coalesced float4) ----
    const int base = g * 16 + s4;          // float4 index of (channel g, spatial s4)
    float4 pm = make_float4(-FLT_MAX, -FLT_MAX, -FLT_MAX, -FLT_MAX);
#pragma unroll 4
    for (int i = 0; i < 16; i++) {
        float4 v = xb[base + i * 1024];    // channel stride = 64 floats = 16 float4
        pm.x = fmaxf(pm.x, v.x); pm.y = fmaxf(pm.y, v.y);
        pm.z = fmaxf(pm.z, v.z); pm.w = fmaxf(pm.w, v.w);
    }
    part[g][s4 * 4 + 0] = pm.x;
    part[g][s4 * 4 + 1] = pm.y;
    part[g][s4 * 4 + 2] = pm.z;
    part[g][s4 * 4 + 3] = pm.w;
    __syncthreads();

    if (tid < 64) {
        float mm = part[0][tid];
#pragma unroll
        for (int gg = 1; gg < 64; gg++) mm = fmaxf(mm, part[gg][tid]);
        m_sh[tid] = mm;
    }
    __syncthreads();

    // ---- Phase 2: 2x2 windows + gumbel scores ----
    if (tid < 64) {
        int w  = tid >> 2, c = tid & 3;        // window 0..15, element 0..3
        int ph = w >> 2,  pw = w & 3;
        int dh = c >> 1,  dw = c & 1;
        float v = m_sh[(2 * ph + dh) * 8 + (2 * pw + dw)];
        wraw[w][c] = v;
        float vc = (isnan(v) || isinf(v) || v < 0.0f) ? EPSV : v;
        wcl[w][c] = vc;
        unsigned l = ((unsigned)b * 16u + (unsigned)w) * 4u + (unsigned)c;
        wsc[w][c] = vc + jax_gumbel_at(l);
    }
    __syncthreads();

    // ---- Phase 3a: per-window sample/max/avg -> pre[4x4] ----
    if (tid < 16) {
        int w = tid;
        float s0 = wsc[w][0]; int bi = 0;
        if (wsc[w][1] > s0) { s0 = wsc[w][1]; bi = 1; }
        if (wsc[w][2] > s0) { s0 = wsc[w][2]; bi = 2; }
        if (wsc[w][3] > s0) { s0 = wsc[w][3]; bi = 3; }
        float mo2 = wcl[w][bi];
        float a = wraw[w][0], bb = wraw[w][1], cc = wraw[w][2], dd = wraw[w][3];
        float mo3 = fmaxf(fmaxf(a, bb), fmaxf(cc, dd));
        float ao4 = (a + bb + cc + dd) * 0.25f;
        pre[w] = 0.1f * mo2 + 0.6f * mo3 + 0.3f * ao4;
    }
    __syncthreads();

    // ---- Phase 3b: 3x3 conv (1->1, no bias, zero pad) on 4x4 ----
    if (tid < 16) {
        int p = tid >> 2, q = tid & 3;
        float acc = 0.0f;
#pragma unroll
        for (int dh = 0; dh < 3; dh++)
#pragma unroll
            for (int dw = 0; dw < 3; dw++) {
                int r = p + dh - 1, cq = q + dw - 1;
                if (r >= 0 && r < 4 && cq >= 0 && cq < 4)
                    acc += pre[r * 4 + cq] * w11[dh * 3 + dw];
            }
        c4s[tid] = acc;
    }
    __syncthreads();

    // ---- Phase 3c: bilinear resize 4->8 (half-pixel, edge clamp) ----
    if (tid < 64) {
        int oh = tid >> 3, ow = tid & 7;
        float th = 0.5f * oh - 0.25f, tw = 0.5f * ow - 0.25f;
        float fh = floorf(th), fw = floorf(tw);
        int ih = (int)fh, iw = (int)fw;
        float ah = th - fh, aw = tw - fw;
        int h0 = max(ih, 0),     h1 = min(ih + 1, 3);
        int w0 = max(iw, 0),     w1 = min(iw + 1, 3);
        float v = (1.0f - ah) * ((1.0f - aw) * c4s[h0 * 4 + w0] + aw * c4s[h0 * 4 + w1])
                +         ah  * ((1.0f - aw) * c4s[h1 * 4 + w0] + aw * c4s[h1 * 4 + w1]);
        out2s[tid] = v;
    }
    __syncthreads();

    // ---- Phase 4a: conv5 (2->4, 3x3, bias, zero pad) + relu on 8x8 ----
    if (tid < 64) {
        int p = tid >> 3, q = tid & 7;
#pragma unroll
        for (int o = 0; o < 4; o++) {
            float acc = b5[o];
#pragma unroll
            for (int dh = 0; dh < 3; dh++)
#pragma unroll
                for (int dw = 0; dw < 3; dw++) {
                    int r = p + dh - 1, cq = q + dw - 1;
                    if (r >= 0 && r < 8 && cq >= 0 && cq < 8) {
                        int idx = r * 8 + cq;
                        acc += m_sh [idx] * w5[((o * 2 + 0) * 3 + dh) * 3 + dw]
                             + out2s[idx] * w5[((o * 2 + 1) * 3 + dh) * 3 + dw];
                    }
                }
            hid[o][tid] = fmaxf(acc, 0.0f);
        }
    }
    __syncthreads();

    // ---- Phase 4b: conv6 (4->1, 3x3, bias) + sigmoid ----
    if (tid < 64) {
        int p = tid >> 3, q = tid & 7;
        float acc = b6[0];
#pragma unroll
        for (int i2 = 0; i2 < 4; i2++)
#pragma unroll
            for (int dh = 0; dh < 3; dh++)
#pragma unroll
                for (int dw = 0; dw < 3; dw++) {
                    int r = p + dh - 1, cq = q + dw - 1;
                    if (r >= 0 && r < 8 && cq >= 0 && cq < 8)
                        acc += hid[i2][r * 8 + cq] * w6[(i2 * 3 + dh) * 3 + dw];
                }
        gate[tid] = 1.0f / (1.0f + expf(-acc));
    }
    __syncthreads();

    // ---- Phase 5: out = relu(x * gate), re-read x (L2 hit), streaming ----
    float4 g4 = *(const float4*)&gate[s4 * 4];
    float4* ob = (float4*)(out + ((size_t)b << 16));
#pragma unroll 4
    for (int i = 0; i < 16; i++) {
        int idx = base + i * 1024;
        float4 v = __ldcs(&xb[idx]);
        v.x = fmaxf(v.x * g4.x, 0.0f);
        v.y = fmaxf(v.y * g4.y, 0.0f);
        v.z = fmaxf(v.z * g4.z, 0.0f);
        v.w = fmaxf(v.w * g4.w, 0.0f);
        __stcs(&ob[idx], v);
    }
}

extern "C" void kernel_launch(void* const* d_in, const int* in_sizes, int n_in,
                              void* d_out, int out_size)
{
    const float* x   = (const float*)d_in[0];
    const float* w11 = (const float*)d_in[1];
    const float* w5  = (const float*)d_in[2];
    const float* b5  = (const float*)d_in[3];
    const float* w6  = (const float*)d_in[4];
    const float* b6  = (const float*)d_in[5];
    float* out = (float*)d_out;

    sa_fused_kernel<<<512, 1024>>>(x, w11, w5, b5, w6, b6, out);
}